// round 13
// baseline (speedup 1.0000x reference)
#include <cuda_runtime.h>

#define NB 32
#define NA 5
#define NC 80
#define NH 76
#define NW 76
#define HW (NH*NW)            // 5776
#define HW4 (HW/4)            // 1444
#define MAXT 50
#define NCELL (NB*NA*HW)      // 924160
#define CHS (NA*(5+NC))       // 425
#define CPB (NA*HW)           // 28880 cells per batch
#define NBLK (NB*MAXT)        // 1600
#define BT 128                // threads per block (single-wave residency)

__constant__ float c_aw[5] = {1.3221f, 3.19275f, 5.05587f, 9.47112f, 11.2364f};
__constant__ float c_ah[5] = {1.73145f, 4.00944f, 8.09892f, 4.84053f, 10.0071f};

// static scratch — no allocation. Epoch protocol: no clearing pass needed.
__device__ unsigned g_mark[NCELL];      // last-claim epoch per cell (BSS zero)
__device__ unsigned g_epoch = 1;        // != 0 initially
__device__ unsigned g_count = 0;        // finished-block counter
__device__ float    g_part[NBLK];       // per-block partial sums (no atomics)

// MUFU-lean sigmoid: 1 EX2 + bit-trick reciprocal (2 Newton steps on the FMA pipe).
// d = 1 + e^{-|v|} in (1,2]; seed rel err ~5%, two Newtons -> ~6e-6.
__device__ __forceinline__ float sigm(float v) {
    float u = __expf(-fabsf(v));              // EX2 (1 MUFU)
    float d = 1.f + u;
    float y = __uint_as_float(0x7EF311C2u - __float_as_uint(d));
    y = y * (2.f - d*y);
    y = y * (2.f - d*y);                      // y ~= 1/d
    return (v >= 0.f) ? y : u*y;              // sigm(-|v|) = u/(1+u)
}

// ================================================================ main (single kernel, 1600 blocks x 128, one wave)
__global__ __launch_bounds__(BT, 11) void k_main(const float* __restrict__ out,
                                                 const float* __restrict__ tgt,
                                                 float* __restrict__ res) {
    int blk = blockIdx.x;
    int b = blk / MAXT, t = blk - b*MAXT;
    int tid = threadIdx.x;
    unsigned ep = g_epoch;

    float accA = 0.f;       // net conf^2 sum (x0.5 at the end)
    float contribM = 0.f;   // matched terms (already scaled)

    // ---- phase A: this block's contiguous slice of the full conf^2 sum ----
    {
        const int per = (NCELL/4 + NBLK - 1) / NBLK;   // 145
        int q0 = blk * per;
        int q1 = min(NCELL/4, q0 + per);
        for (int q = q0 + tid; q < q1; q += BT) {
            int p   = q / HW4;              // b*5+a
            int hw4 = q - p*HW4;
            int bb  = p / NA, aa = p - bb*NA;
            float4 c4 = *(const float4*)(out + (size_t)(bb*CHS + aa*(5+NC) + 4)*HW + hw4*4);
            float s0 = sigm(c4.x), s1 = sigm(c4.y), s2 = sigm(c4.z), s3 = sigm(c4.w);
            accA += s0*s0 + s1*s1 + s2*s2 + s3*s3;
        }
    }

    // ---- target table: ballots instead of serial loops ----
    __shared__ int      s_cell[64];
    __shared__ unsigned s_msk[2];      // ok ballots (warp0, warp1)
    __shared__ unsigned s_cfl[2];      // conflict ballots
    __shared__ float    s_par[8];      // gx gy gw gh | (int) bn gi gj cls
    __shared__ float    s_int[4*NA];   // per-anchor raw-logit intervals: wlo whi hlo hhi

    if (tid < 64) {
        bool okf = false; int cellv = 0;
        if (tid < MAXT) {
            const float* tp = tgt + (b*MAXT + tid)*5;
            okf = (tp[1] != 0.f);
            float gx = tp[1]*NW, gy = tp[2]*NH, gw = tp[3]*NW, gh = tp[4]*NH;
            float best = -1.f; int bn = 0;
            #pragma unroll
            for (int a = 0; a < NA; a++) {
                float aw = c_aw[a], ah = c_ah[a];
                float inter = fminf(gw, aw) * fminf(gh, ah);
                float iou   = __fdividef(inter, gw*gh + aw*ah - inter);
                if (iou > best) { best = iou; bn = a; }
            }
            int gi = max(0, min(NW-1, (int)gx));
            int gj = max(0, min(NH-1, (int)gy));
            cellv = (bn*NH + gj)*NW + gi;
            if (tid == t) {
                s_par[0] = gx; s_par[1] = gy; s_par[2] = gw; s_par[3] = gh;
                ((int*)s_par)[4] = bn; ((int*)s_par)[5] = gi; ((int*)s_par)[6] = gj;
                ((int*)s_par)[7] = (int)tp[0];
            }
        }
        s_cell[tid] = cellv;
        unsigned bal = __ballot_sync(0xFFFFFFFFu, okf);
        if ((tid & 31) == 0) s_msk[tid >> 5] = bal;
    }
    __syncthreads();

    unsigned long long okm = (unsigned long long)s_msk[0]
                           | ((unsigned long long)s_msk[1] << 32);
    int validT = (((~okm) & ((2ull << t) - 1ull)) == 0ull);
    unsigned long long inv = ~okm;
    int V = inv ? (__ffsll((long long)inv) - 1) : 64;     // valid targets are [0, V)
    int cellT = s_cell[t];

    if (tid < 64) {
        bool cf = (tid > t) && (tid < V) && (s_cell[tid] == cellT);
        unsigned bal = __ballot_sync(0xFFFFFFFFu, cf);
        if ((tid & 31) == 0) s_cfl[tid >> 5] = bal;
    }
    // anchor prefilter intervals
    if (tid >= 64 && tid < 64 + NA) {
        int a = tid - 64;
        float gw = s_par[2], gh = s_par[3];
        s_int[a*4+0] = __logf(__fdividef(0.6f*gw, c_aw[a])) - 1e-3f;
        s_int[a*4+1] = __logf(__fdividef(gw, 0.6f*c_aw[a])) + 1e-3f;
        s_int[a*4+2] = __logf(__fdividef(0.6f*gh, c_ah[a])) - 1e-3f;
        s_int[a*4+3] = __logf(__fdividef(gh, 0.6f*c_ah[a])) + 1e-3f;
    }
    __syncthreads();
    int winner = validT && !(s_cfl[0] | s_cfl[1]);

    int bn = ((const int*)s_par)[4];
    int gi = ((const int*)s_par)[5];
    int gj = ((const int*)s_par)[6];
    int obase = (b*CHS + bn*(5+NC))*HW + gj*NW + gi;

    // ---- phase B: matched-cell loss (winner blocks; 3 warps, 80-wide log-softmax) ----
    if (winner) {
        __shared__ float sm[3], ss[3];
        int lane = tid & 31, wid = tid >> 5;
        const float* lg = out + obase + 5*HW;
        if (tid < 96) {
            unsigned mask = 0xFFFFFFFFu;
            float v = (tid < NC) ? __ldg(lg + tid*HW) : -1e30f;
            float m = v;
            #pragma unroll
            for (int off = 16; off > 0; off >>= 1) m = fmaxf(m, __shfl_xor_sync(mask, m, off));
            if (lane == 0) sm[wid] = m;
        }
        __syncthreads();
        if (tid < 96) {
            unsigned mask = 0xFFFFFFFFu;
            float mx = fmaxf(sm[0], fmaxf(sm[1], sm[2]));
            float v = (tid < NC) ? __ldg(lg + tid*HW) : -1e30f;
            float e = (tid < NC) ? __expf(v - mx) : 0.f;
            #pragma unroll
            for (int off = 16; off > 0; off >>= 1) e += __shfl_xor_sync(mask, e, off);
            if (lane == 0) ss[wid] = e;
        }
        __syncthreads();
        if (tid == 0) {
            float gx = s_par[0], gy = s_par[1], gw = s_par[2], gh = s_par[3];
            float mxv = fmaxf(sm[0], fmaxf(sm[1], sm[2]));
            float s   = ss[0] + ss[1] + ss[2];
            int   tc  = ((const int*)s_par)[7];
            float ce  = mxv + __logf(s) - __ldg(lg + tc*HW);

            float o0 = out[obase],      o1 = out[obase+HW];
            float o2 = out[obase+2*HW], o3 = out[obase+3*HW];
            float conf = sigm(out[obase+4*HW]);
            float mpx = sigm(o0) + (float)gi;
            float mpy = sigm(o1) + (float)gj;
            float mpw = __expf(o2) * c_aw[bn];
            float mph = __expf(o3) * c_ah[bn];
            float lx = fminf(gx - 0.5f*gw, mpx - 0.5f*mpw);
            float Rx = fmaxf(gx + 0.5f*gw, mpx + 0.5f*mpw);
            float ly = fminf(gy - 0.5f*gh, mpy - 0.5f*mph);
            float Ry = fmaxf(gy + 0.5f*gh, mpy + 0.5f*mph);
            float cw = gw + mpw - (Rx - lx);
            float ch = gh + mph - (Ry - ly);
            float inter = (cw <= 0.f || ch <= 0.f) ? 0.f : cw*ch;
            float t_iou = __fdividef(inter, gw*gh + mpw*mph - inter);

            float dx = sigm(o0) - (gx - (float)gi);
            float dy = sigm(o1) - (gy - (float)gj);
            float dw = o2 - __logf(__fdividef(gw, c_aw[bn]));
            float dh = o3 - __logf(__fdividef(gh, c_ah[bn]));
            float dc = conf - t_iou;
            contribM = 0.5f*(dx*dx + dy*dy + dw*dw + dh*dh) + 2.5f*dc*dc + ce;

            unsigned old = atomicExch(&g_mark[b*CPB + cellT], ep);
            if (old != ep) accA -= conf*conf;
        }
    }

    // ---- phase C: raster, EXACT 0.4 window + interval prefilter ----
    // IoU>0.6 => |px-gx| < 0.4*gw with px in (i,i+1)
    //         => i in [floor(gx-0.4gw), floor(gx+0.4gw)] exactly; 1e-3 fp slack.
    if (validT) {
        float gx = s_par[0], gy = s_par[1], gw = s_par[2], gh = s_par[3];
        float gx0 = gx - 0.5f*gw, gx1 = gx + 0.5f*gw;
        float gy0 = gy - 0.5f*gh, gy1 = gy + 0.5f*gh;
        float g375 = 0.375f * gw * gh;

        int i0 = max(0,    (int)floorf(gx - 0.4f*gw - 1e-3f));
        int i1 = min(NW-1, (int)floorf(gx + 0.4f*gw + 1e-3f));
        int j0 = max(0,    (int)floorf(gy - 0.4f*gh - 1e-3f));
        int j1 = min(NH-1, (int)floorf(gy + 0.4f*gh + 1e-3f));
        int i0a = i0 & ~3;
        int nGi = (i1 - i0a + 4) >> 2;        // group starts <= 72, cells <= 75
        int wj  = j1 - j0 + 1;
        int perA = nGi * wj;
        int tot  = perA * NA;
        unsigned Mp = 0xFFFFFFFFu / (unsigned)perA + 1u;   // exact div magic (k < 2^16)
        unsigned Mg = 0xFFFFFFFFu / (unsigned)nGi  + 1u;

        const float* bbase = out + (size_t)b*CHS*HW;

        for (int k = tid; k < tot; k += BT) {
            unsigned a  = (unsigned)(((unsigned long long)(unsigned)k * Mp) >> 32);
            unsigned rr = (unsigned)k - a*(unsigned)perA;
            unsigned jq = (unsigned)(((unsigned long long)rr * Mg) >> 32);
            int j  = j0 + (int)jq;
            int ib = i0a + (int)((rr - jq*(unsigned)nGi) << 2);
            const float* pb = bbase + (size_t)a*(5+NC)*HW + (j*NW + ib);

            float4 v2 = __ldg((const float4*)(pb + 2*HW));
            float4 v3 = __ldg((const float4*)(pb + 3*HW));
            float wlo = s_int[a*4+0], whi = s_int[a*4+1];
            float hlo = s_int[a*4+2], hhi = s_int[a*4+3];
            bool k0 = (v2.x > wlo) & (v2.x < whi) & (v3.x > hlo) & (v3.x < hhi);
            bool k1 = (v2.y > wlo) & (v2.y < whi) & (v3.y > hlo) & (v3.y < hhi);
            bool k2 = (v2.z > wlo) & (v2.z < whi) & (v3.z > hlo) & (v3.z < hhi);
            bool k3 = (v2.w > wlo) & (v2.w < whi) & (v3.w > hlo) & (v3.w < hhi);
            if (!(k0 | k1 | k2 | k3)) continue;

            float4 v0 = __ldg((const float4*)(pb));
            float4 v1 = __ldg((const float4*)(pb + HW));
            const float* q0 = &v0.x; const float* q1 = &v1.x;
            const float* qw = &v2.x; const float* qh = &v3.x;
            bool kk[4] = {k0, k1, k2, k3};
            #pragma unroll
            for (int u = 0; u < 4; u++) {
                if (!kk[u]) continue;
                int i = ib + u;
                float px = sigm(q0[u]) + (float)i;
                float py = sigm(q1[u]) + (float)j;
                float pw = __expf(qw[u]) * c_aw[a];
                float ph = __expf(qh[u]) * c_ah[a];
                float cw = pw + gw - (fmaxf(px + 0.5f*pw, gx1) - fminf(px - 0.5f*pw, gx0));
                float ch = ph + gh - (fmaxf(py + 0.5f*ph, gy1) - fminf(py - 0.5f*ph, gy0));
                if (cw > 0.f && ch > 0.f) {
                    float inter = cw * ch;
                    if (inter > 0.375f*pw*ph + g375) {      // exact: iou > 0.6
                        int cib = ((int)a*NH + j)*NW + i;
                        unsigned old = atomicExch(&g_mark[b*CPB + cib], ep);
                        if (old != ep) {
                            float cv = sigm(__ldg(pb + 4*HW + u));
                            accA -= cv*cv;
                        }
                    }
                }
            }
        }
    }

    // ---- block reduction (4 warps) -> contention-free partial store; last block reduces ----
    float v = 0.5f*accA + contribM;
    unsigned mask = 0xFFFFFFFFu;
    #pragma unroll
    for (int off = 16; off > 0; off >>= 1) v += __shfl_down_sync(mask, v, off);
    __shared__ float sw[4];
    __shared__ int   s_last;
    int lane = tid & 31, wid = tid >> 5;
    if (lane == 0) sw[wid] = v;
    __syncthreads();
    if (tid < 32) {
        v = (lane < 4) ? sw[lane] : 0.f;
        #pragma unroll
        for (int off = 2; off > 0; off >>= 1) v += __shfl_down_sync(mask, v, off);
        if (lane == 0) {
            g_part[blk] = v;
            __threadfence();
            unsigned done = atomicAdd(&g_count, 1u);
            s_last = (done == NBLK - 1);
        }
    }
    __syncthreads();
    if (s_last) {
        double d = 0.0;
        for (int k = tid; k < NBLK; k += BT) d += (double)g_part[k];
        #pragma unroll
        for (int off = 16; off > 0; off >>= 1) d += __shfl_down_sync(mask, d, off);
        __shared__ double sd[4];
        if (lane == 0) sd[wid] = d;
        __syncthreads();
        if (tid < 32) {
            d = (lane < 4) ? sd[lane] : 0.0;
            #pragma unroll
            for (int off = 2; off > 0; off >>= 1) d += __shfl_down_sync(mask, d, off);
            if (lane == 0) {
                res[0] = (float)d;
                g_count = 0;
                g_epoch = ep + 1;
            }
        }
    }
}

// ================================================================ launch
extern "C" void kernel_launch(void* const* d_in, const int* in_sizes, int n_in,
                              void* d_out, int out_size) {
    const float* out = (const float*)d_in[0];   // (32, 425, 76, 76)
    const float* tgt = (const float*)d_in[1];   // (32, 250)
    float* res = (float*)d_out;

    k_main<<<NBLK, BT>>>(out, tgt, res);
}

// round 14
// speedup vs baseline: 1.1084x; 1.1084x over previous
#include <cuda_runtime.h>

#define NB 32
#define NA 5
#define NC 80
#define NH 76
#define NW 76
#define HW (NH*NW)            // 5776
#define HW4 (HW/4)            // 1444
#define MAXT 50
#define NCELL (NB*NA*HW)      // 924160
#define CHS (NA*(5+NC))       // 425
#define CPB (NA*HW)           // 28880 cells per batch
#define NBLK (NB*MAXT)        // 1600
#define BT 128                // threads per block (single-wave residency)

__constant__ float c_aw[5] = {1.3221f, 3.19275f, 5.05587f, 9.47112f, 11.2364f};
__constant__ float c_ah[5] = {1.73145f, 4.00944f, 8.09892f, 4.84053f, 10.0071f};

// static scratch — no allocation. Epoch protocol: no clearing pass needed.
__device__ unsigned g_mark[NCELL];      // last-claim epoch per cell (BSS zero)
__device__ unsigned g_epoch = 1;        // != 0 initially
__device__ unsigned g_count = 0;        // finished-block counter
__device__ float    g_part[NBLK];       // per-block partial sums (no atomics)

__device__ __forceinline__ float sigm(float v) {
    return __fdividef(1.f, 1.f + __expf(-v));
}

// ================================================================ main (single kernel, 1600 blocks x 128, one wave, 12/SM)
__global__ __launch_bounds__(BT, 12) void k_main(const float* __restrict__ out,
                                                 const float* __restrict__ tgt,
                                                 float* __restrict__ res) {
    int blk = blockIdx.x;
    int b = blk / MAXT, t = blk - b*MAXT;
    int tid = threadIdx.x;
    unsigned ep = g_epoch;

    float accA = 0.f;       // net conf^2 sum (x0.5 at the end)
    float contribM = 0.f;   // matched terms (already scaled)

    // ---- phase A: this block's contiguous slice of the full conf^2 sum ----
    {
        const int per = (NCELL/4 + NBLK - 1) / NBLK;   // 145
        int q0 = blk * per;
        int q1 = min(NCELL/4, q0 + per);
        for (int q = q0 + tid; q < q1; q += BT) {
            int p   = q / HW4;              // b*5+a
            int hw4 = q - p*HW4;
            int bb  = p / NA, aa = p - bb*NA;
            float4 c4 = *(const float4*)(out + (size_t)(bb*CHS + aa*(5+NC) + 4)*HW + hw4*4);
            float s0 = sigm(c4.x), s1 = sigm(c4.y), s2 = sigm(c4.z), s3 = sigm(c4.w);
            accA += s0*s0 + s1*s1 + s2*s2 + s3*s3;
        }
    }

    // ---- target table: ballots instead of serial loops ----
    __shared__ int      s_cell[64];
    __shared__ unsigned s_msk[2];      // ok ballots (warp0, warp1)
    __shared__ unsigned s_cfl[2];      // conflict ballots
    __shared__ float    s_par[8];      // gx gy gw gh | (int) bn gi gj cls
    __shared__ float    s_int[4*NA];   // per-anchor raw-logit intervals: wlo whi hlo hhi

    if (tid < 64) {
        bool okf = false; int cellv = 0;
        if (tid < MAXT) {
            const float* tp = tgt + (b*MAXT + tid)*5;
            okf = (tp[1] != 0.f);
            float gx = tp[1]*NW, gy = tp[2]*NH, gw = tp[3]*NW, gh = tp[4]*NH;
            float best = -1.f; int bn = 0;
            #pragma unroll
            for (int a = 0; a < NA; a++) {
                float aw = c_aw[a], ah = c_ah[a];
                float inter = fminf(gw, aw) * fminf(gh, ah);
                float iou   = __fdividef(inter, gw*gh + aw*ah - inter);
                if (iou > best) { best = iou; bn = a; }
            }
            int gi = max(0, min(NW-1, (int)gx));
            int gj = max(0, min(NH-1, (int)gy));
            cellv = (bn*NH + gj)*NW + gi;
            if (tid == t) {
                s_par[0] = gx; s_par[1] = gy; s_par[2] = gw; s_par[3] = gh;
                ((int*)s_par)[4] = bn; ((int*)s_par)[5] = gi; ((int*)s_par)[6] = gj;
                ((int*)s_par)[7] = (int)tp[0];
            }
        }
        s_cell[tid] = cellv;
        unsigned bal = __ballot_sync(0xFFFFFFFFu, okf);
        if ((tid & 31) == 0) s_msk[tid >> 5] = bal;
    }
    __syncthreads();

    unsigned long long okm = (unsigned long long)s_msk[0]
                           | ((unsigned long long)s_msk[1] << 32);
    int validT = (((~okm) & ((2ull << t) - 1ull)) == 0ull);
    unsigned long long inv = ~okm;
    int V = inv ? (__ffsll((long long)inv) - 1) : 64;     // valid targets are [0, V)
    int cellT = s_cell[t];

    if (tid < 64) {
        bool cf = (tid > t) && (tid < V) && (s_cell[tid] == cellT);
        unsigned bal = __ballot_sync(0xFFFFFFFFu, cf);
        if ((tid & 31) == 0) s_cfl[tid >> 5] = bal;
    }
    // anchor prefilter intervals
    if (tid >= 64 && tid < 64 + NA) {
        int a = tid - 64;
        float gw = s_par[2], gh = s_par[3];
        s_int[a*4+0] = __logf(__fdividef(0.6f*gw, c_aw[a])) - 1e-3f;
        s_int[a*4+1] = __logf(__fdividef(gw, 0.6f*c_aw[a])) + 1e-3f;
        s_int[a*4+2] = __logf(__fdividef(0.6f*gh, c_ah[a])) - 1e-3f;
        s_int[a*4+3] = __logf(__fdividef(gh, 0.6f*c_ah[a])) + 1e-3f;
    }
    __syncthreads();
    int winner = validT && !(s_cfl[0] | s_cfl[1]);

    int bn = ((const int*)s_par)[4];
    int gi = ((const int*)s_par)[5];
    int gj = ((const int*)s_par)[6];
    int obase = (b*CHS + bn*(5+NC))*HW + gj*NW + gi;

    // ---- phase B: matched-cell loss (winner blocks; 3 warps, 80-wide log-softmax) ----
    if (winner) {
        __shared__ float sm[3], ss[3];
        int lane = tid & 31, wid = tid >> 5;
        const float* lg = out + obase + 5*HW;
        if (tid < 96) {
            unsigned mask = 0xFFFFFFFFu;
            float v = (tid < NC) ? __ldg(lg + tid*HW) : -1e30f;
            float m = v;
            #pragma unroll
            for (int off = 16; off > 0; off >>= 1) m = fmaxf(m, __shfl_xor_sync(mask, m, off));
            if (lane == 0) sm[wid] = m;
        }
        __syncthreads();
        if (tid < 96) {
            unsigned mask = 0xFFFFFFFFu;
            float mx = fmaxf(sm[0], fmaxf(sm[1], sm[2]));
            float v = (tid < NC) ? __ldg(lg + tid*HW) : -1e30f;
            float e = (tid < NC) ? __expf(v - mx) : 0.f;
            #pragma unroll
            for (int off = 16; off > 0; off >>= 1) e += __shfl_xor_sync(mask, e, off);
            if (lane == 0) ss[wid] = e;
        }
        __syncthreads();
        if (tid == 0) {
            float gx = s_par[0], gy = s_par[1], gw = s_par[2], gh = s_par[3];
            float mxv = fmaxf(sm[0], fmaxf(sm[1], sm[2]));
            float s   = ss[0] + ss[1] + ss[2];
            int   tc  = ((const int*)s_par)[7];
            float ce  = mxv + __logf(s) - __ldg(lg + tc*HW);

            float o0 = out[obase],      o1 = out[obase+HW];
            float o2 = out[obase+2*HW], o3 = out[obase+3*HW];
            float conf = sigm(out[obase+4*HW]);
            float mpx = sigm(o0) + (float)gi;
            float mpy = sigm(o1) + (float)gj;
            float mpw = __expf(o2) * c_aw[bn];
            float mph = __expf(o3) * c_ah[bn];
            float lx = fminf(gx - 0.5f*gw, mpx - 0.5f*mpw);
            float Rx = fmaxf(gx + 0.5f*gw, mpx + 0.5f*mpw);
            float ly = fminf(gy - 0.5f*gh, mpy - 0.5f*mph);
            float Ry = fmaxf(gy + 0.5f*gh, mpy + 0.5f*mph);
            float cw = gw + mpw - (Rx - lx);
            float ch = gh + mph - (Ry - ly);
            float inter = (cw <= 0.f || ch <= 0.f) ? 0.f : cw*ch;
            float t_iou = __fdividef(inter, gw*gh + mpw*mph - inter);

            float dx = sigm(o0) - (gx - (float)gi);
            float dy = sigm(o1) - (gy - (float)gj);
            float dw = o2 - __logf(__fdividef(gw, c_aw[bn]));
            float dh = o3 - __logf(__fdividef(gh, c_ah[bn]));
            float dc = conf - t_iou;
            contribM = 0.5f*(dx*dx + dy*dy + dw*dw + dh*dh) + 2.5f*dc*dc + ce;

            unsigned old = atomicExch(&g_mark[b*CPB + cellT], ep);
            if (old != ep) accA -= conf*conf;
        }
    }

    // ---- phase C: raster, EXACT 0.4 window + interval prefilter ----
    // IoU>0.6 => |px-gx| < 0.4*gw with px in (i,i+1)
    //         => i in [floor(gx-0.4gw), floor(gx+0.4gw)] exactly; 1e-3 fp slack.
    if (validT) {
        float gx = s_par[0], gy = s_par[1], gw = s_par[2], gh = s_par[3];
        float gx0 = gx - 0.5f*gw, gx1 = gx + 0.5f*gw;
        float gy0 = gy - 0.5f*gh, gy1 = gy + 0.5f*gh;
        float g375 = 0.375f * gw * gh;

        int i0 = max(0,    (int)floorf(gx - 0.4f*gw - 1e-3f));
        int i1 = min(NW-1, (int)floorf(gx + 0.4f*gw + 1e-3f));
        int j0 = max(0,    (int)floorf(gy - 0.4f*gh - 1e-3f));
        int j1 = min(NH-1, (int)floorf(gy + 0.4f*gh + 1e-3f));
        int i0a = i0 & ~3;
        int nGi = (i1 - i0a + 4) >> 2;        // group starts <= 72, cells <= 75
        int wj  = j1 - j0 + 1;
        int perA = nGi * wj;
        int tot  = perA * NA;
        unsigned Mp = 0xFFFFFFFFu / (unsigned)perA + 1u;   // exact div magic (k < 2^16)
        unsigned Mg = 0xFFFFFFFFu / (unsigned)nGi  + 1u;

        const float* bbase = out + (size_t)b*CHS*HW;

        for (int k = tid; k < tot; k += BT) {
            unsigned a  = (unsigned)(((unsigned long long)(unsigned)k * Mp) >> 32);
            unsigned rr = (unsigned)k - a*(unsigned)perA;
            unsigned jq = (unsigned)(((unsigned long long)rr * Mg) >> 32);
            int j  = j0 + (int)jq;
            int ib = i0a + (int)((rr - jq*(unsigned)nGi) << 2);
            const float* pb = bbase + (size_t)a*(5+NC)*HW + (j*NW + ib);

            float4 v2 = __ldg((const float4*)(pb + 2*HW));
            float4 v3 = __ldg((const float4*)(pb + 3*HW));
            float wlo = s_int[a*4+0], whi = s_int[a*4+1];
            float hlo = s_int[a*4+2], hhi = s_int[a*4+3];
            bool k0 = (v2.x > wlo) & (v2.x < whi) & (v3.x > hlo) & (v3.x < hhi);
            bool k1 = (v2.y > wlo) & (v2.y < whi) & (v3.y > hlo) & (v3.y < hhi);
            bool k2 = (v2.z > wlo) & (v2.z < whi) & (v3.z > hlo) & (v3.z < hhi);
            bool k3 = (v2.w > wlo) & (v2.w < whi) & (v3.w > hlo) & (v3.w < hhi);
            if (!(k0 | k1 | k2 | k3)) continue;

            float4 v0 = __ldg((const float4*)(pb));
            float4 v1 = __ldg((const float4*)(pb + HW));
            const float* q0 = &v0.x; const float* q1 = &v1.x;
            const float* qw = &v2.x; const float* qh = &v3.x;
            bool kk[4] = {k0, k1, k2, k3};
            #pragma unroll
            for (int u = 0; u < 4; u++) {
                if (!kk[u]) continue;
                int i = ib + u;
                float px = sigm(q0[u]) + (float)i;
                float py = sigm(q1[u]) + (float)j;
                float pw = __expf(qw[u]) * c_aw[a];
                float ph = __expf(qh[u]) * c_ah[a];
                float cw = pw + gw - (fmaxf(px + 0.5f*pw, gx1) - fminf(px - 0.5f*pw, gx0));
                float ch = ph + gh - (fmaxf(py + 0.5f*ph, gy1) - fminf(py - 0.5f*ph, gy0));
                if (cw > 0.f && ch > 0.f) {
                    float inter = cw * ch;
                    if (inter > 0.375f*pw*ph + g375) {      // exact: iou > 0.6
                        int cib = ((int)a*NH + j)*NW + i;
                        unsigned old = atomicExch(&g_mark[b*CPB + cib], ep);
                        if (old != ep) {
                            float cv = sigm(__ldg(pb + 4*HW + u));
                            accA -= cv*cv;
                        }
                    }
                }
            }
        }
    }

    // ---- block reduction (4 warps) -> contention-free partial store; last block reduces ----
    float v = 0.5f*accA + contribM;
    unsigned mask = 0xFFFFFFFFu;
    #pragma unroll
    for (int off = 16; off > 0; off >>= 1) v += __shfl_down_sync(mask, v, off);
    __shared__ float sw[4];
    __shared__ int   s_last;
    int lane = tid & 31, wid = tid >> 5;
    if (lane == 0) sw[wid] = v;
    __syncthreads();
    if (tid < 32) {
        v = (lane < 4) ? sw[lane] : 0.f;
        #pragma unroll
        for (int off = 2; off > 0; off >>= 1) v += __shfl_down_sync(mask, v, off);
        if (lane == 0) {
            g_part[blk] = v;
            __threadfence();
            unsigned done = atomicAdd(&g_count, 1u);
            s_last = (done == NBLK - 1);
        }
    }
    __syncthreads();
    if (s_last) {
        double d = 0.0;
        for (int k = tid; k < NBLK; k += BT) d += (double)g_part[k];
        #pragma unroll
        for (int off = 16; off > 0; off >>= 1) d += __shfl_down_sync(mask, d, off);
        __shared__ double sd[4];
        if (lane == 0) sd[wid] = d;
        __syncthreads();
        if (tid < 32) {
            d = (lane < 4) ? sd[lane] : 0.0;
            #pragma unroll
            for (int off = 2; off > 0; off >>= 1) d += __shfl_down_sync(mask, d, off);
            if (lane == 0) {
                res[0] = (float)d;
                g_count = 0;
                g_epoch = ep + 1;
            }
        }
    }
}

// ================================================================ launch
extern "C" void kernel_launch(void* const* d_in, const int* in_sizes, int n_in,
                              void* d_out, int out_size) {
    const float* out = (const float*)d_in[0];   // (32, 425, 76, 76)
    const float* tgt = (const float*)d_in[1];   // (32, 250)
    float* res = (float*)d_out;

    k_main<<<NBLK, BT>>>(out, tgt, res);
}